// round 3
// baseline (speedup 1.0000x reference)
#include <cuda_runtime.h>
#include <math.h>

// Problem constants
#define NTOK   9216      // B*H*W tokens
#define CCH    512       // channels
#define HW     2304      // H*W
#define BATCH  4
#define BN_EPS 1e-5f

// Attention row-chunking: process queries in chunks to bound scratch memory
#define QCHUNK 2304      // rows per chunk
#define NCHUNK (NTOK / QCHUNK)   // 4

// GEMM tile config
#define BM 128
#define BNT 128
#define BK 16
#define TM 8
#define TN 8
#define PAD 4     // smem row padding

// ---------------------------------------------------------------------------
// Static device scratch (no allocations allowed).  ~142 MB total.
// ---------------------------------------------------------------------------
__device__ float g_LIN[3][NTOK * CCH];               // 0: xt@w_rgb, 1: lhs, 2: rhs (54MB)
__device__ float g_LOGITS[(size_t)QCHUNK * NTOK];    // 85 MB chunk scratch
__device__ float g_RMAX[NTOK];
__device__ float g_RINV[NTOK];
__device__ float g_ENH[NTOK * CCH];
__device__ float g_Y[NTOK * CCH];                    // decoder output, token-major
__device__ float g_PART[2 * 72 * CCH];               // BN partial sums / sumsq
__device__ float g_SCALE[CCH];
__device__ float g_SHIFT[CCH];

// ---------------------------------------------------------------------------
// Kernel 1: input 1x1 convs (per-token linear).  grid.z selects which.
//   A read directly from (B,C,H,W) layout: for a 128-token tile (fixed b,
//   since 2304 % 128 == 0) each channel row is 128 contiguous floats.
//   out[n][o] = sum_c A[n][c] * W[o][c] + bias[o]
// ---------------------------------------------------------------------------
__global__ __launch_bounds__(256) void linear_kernel(
    const float* __restrict__ x, const float* __restrict__ dep,
    const float* __restrict__ w_rgb, const float* __restrict__ b_rgb,
    const float* __restrict__ w_lhs, const float* __restrict__ b_lhs,
    const float* __restrict__ w_rhs, const float* __restrict__ b_rhs)
{
    const int which = blockIdx.z;
    const float* __restrict__ A    = (which == 0) ? x : dep;
    const float* __restrict__ W    = (which == 0) ? w_rgb : (which == 1 ? w_lhs : w_rhs);
    const float* __restrict__ bias = (which == 0) ? b_rgb : (which == 1 ? b_lhs : b_rhs);
    float* __restrict__ out = g_LIN[which];

    __shared__ float As[BK][BM + PAD];
    __shared__ float Bs[BK][BNT + PAD];

    const int m0 = blockIdx.y * BM;
    const int n0 = blockIdx.x * BNT;
    const int b  = m0 / HW;
    const int hw0 = m0 % HW;
    const int t  = threadIdx.x;
    const int tx = t % 16, ty = t / 16;

    // A loader: k-row direct copy
    const int lk  = t / 16;    // 0..15 (k within tile)
    const int lcv = t % 16;    // col group
    // B loader: transposed (W is O x C row-major, K contiguous)
    const int brow = t / 4;    // 0..63 (+64)
    const int bkv  = t % 4;

    float acc[TM][TN];
#pragma unroll
    for (int i = 0; i < TM; i++)
#pragma unroll
        for (int j = 0; j < TN; j++) acc[i][j] = 0.f;

    for (int k0 = 0; k0 < CCH; k0 += BK) {
        const float* ap = A + ((size_t)(b * CCH + k0 + lk)) * HW + hw0;
        float4 a0 = *(const float4*)(ap + 4 * lcv);
        float4 a1 = *(const float4*)(ap + 4 * lcv + 64);
        *(float4*)&As[lk][4 * lcv]      = a0;
        *(float4*)&As[lk][4 * lcv + 64] = a1;
#pragma unroll
        for (int r = 0; r < 2; r++) {
            int n = brow + r * 64;
            float4 w4 = *(const float4*)(W + (size_t)(n0 + n) * CCH + k0 + 4 * bkv);
            Bs[4 * bkv + 0][n] = w4.x;
            Bs[4 * bkv + 1][n] = w4.y;
            Bs[4 * bkv + 2][n] = w4.z;
            Bs[4 * bkv + 3][n] = w4.w;
        }
        __syncthreads();
#pragma unroll
        for (int k = 0; k < BK; k++) {
            float af[TM], bf[TN];
#pragma unroll
            for (int i = 0; i < TM; i++) af[i] = As[k][ty * TM + i];
#pragma unroll
            for (int j = 0; j < TN; j++) bf[j] = Bs[k][tx * TN + j];
#pragma unroll
            for (int i = 0; i < TM; i++)
#pragma unroll
                for (int j = 0; j < TN; j++)
                    acc[i][j] = fmaf(af[i], bf[j], acc[i][j]);
        }
        __syncthreads();
    }

#pragma unroll
    for (int i = 0; i < TM; i++) {
        int m = m0 + ty * TM + i;
        float* op = out + (size_t)m * CCH + n0 + tx * TN;
#pragma unroll
        for (int j = 0; j < TN; j++) op[j] = acc[i][j] + bias[n0 + tx * TN + j];
    }
}

// ---------------------------------------------------------------------------
// Kernel 2: logits chunk = LHS[base..base+QCHUNK) @ RHS^T
//   (both N x C row-major, K contiguous)
// ---------------------------------------------------------------------------
__global__ __launch_bounds__(256) void logits_kernel(int base)
{
    const float* __restrict__ Amat = g_LIN[1];
    const float* __restrict__ Bmat = g_LIN[2];

    __shared__ float As[BK][BM + PAD];
    __shared__ float Bs[BK][BNT + PAD];

    const int lm0 = blockIdx.y * BM;       // local row within chunk
    const int m0  = base + lm0;            // global query row
    const int n0  = blockIdx.x * BNT;
    const int t   = threadIdx.x;
    const int tx = t % 16, ty = t / 16;
    const int row = t / 4;     // 0..63 (+64)
    const int kv  = t % 4;

    float acc[TM][TN];
#pragma unroll
    for (int i = 0; i < TM; i++)
#pragma unroll
        for (int j = 0; j < TN; j++) acc[i][j] = 0.f;

    for (int k0 = 0; k0 < CCH; k0 += BK) {
#pragma unroll
        for (int r = 0; r < 2; r++) {
            int m = row + r * 64;
            float4 a4 = *(const float4*)(Amat + (size_t)(m0 + m) * CCH + k0 + 4 * kv);
            As[4 * kv + 0][m] = a4.x;
            As[4 * kv + 1][m] = a4.y;
            As[4 * kv + 2][m] = a4.z;
            As[4 * kv + 3][m] = a4.w;
            int n = row + r * 64;
            float4 b4 = *(const float4*)(Bmat + (size_t)(n0 + n) * CCH + k0 + 4 * kv);
            Bs[4 * kv + 0][n] = b4.x;
            Bs[4 * kv + 1][n] = b4.y;
            Bs[4 * kv + 2][n] = b4.z;
            Bs[4 * kv + 3][n] = b4.w;
        }
        __syncthreads();
#pragma unroll
        for (int k = 0; k < BK; k++) {
            float af[TM], bf[TN];
#pragma unroll
            for (int i = 0; i < TM; i++) af[i] = As[k][ty * TM + i];
#pragma unroll
            for (int j = 0; j < TN; j++) bf[j] = Bs[k][tx * TN + j];
#pragma unroll
            for (int i = 0; i < TM; i++)
#pragma unroll
                for (int j = 0; j < TN; j++)
                    acc[i][j] = fmaf(af[i], bf[j], acc[i][j]);
        }
        __syncthreads();
    }

#pragma unroll
    for (int i = 0; i < TM; i++) {
        int lm = lm0 + ty * TM + i;
        float* op = g_LOGITS + (size_t)lm * NTOK + n0 + tx * TN;
        *(float4*)(op)     = make_float4(acc[i][0], acc[i][1], acc[i][2], acc[i][3]);
        *(float4*)(op + 4) = make_float4(acc[i][4], acc[i][5], acc[i][6], acc[i][7]);
    }
}

// ---------------------------------------------------------------------------
// Kernel 3: row softmax stats (max, 1/sumexp) for a chunk. One block per row.
//   Single pass: online (max, sum) with rescaling, merged across lanes/warps.
// ---------------------------------------------------------------------------
__global__ __launch_bounds__(256) void softmax_kernel(int base)
{
    const int lrow = blockIdx.x;
    const float4* __restrict__ rp = (const float4*)(g_LOGITS + (size_t)lrow * NTOK);
    const int t = threadIdx.x;
    __shared__ float redm[8], reds[8];

    float m = -3.4e38f, s = 0.f;
    for (int i = t; i < NTOK / 4; i += 256) {
        float4 v = rp[i];
        float vm = fmaxf(fmaxf(v.x, v.y), fmaxf(v.z, v.w));
        float nm = fmaxf(m, vm);
        s = s * __expf(m - nm)
          + __expf(v.x - nm) + __expf(v.y - nm) + __expf(v.z - nm) + __expf(v.w - nm);
        m = nm;
    }
#pragma unroll
    for (int o = 16; o; o >>= 1) {
        float om = __shfl_xor_sync(0xffffffffu, m, o);
        float os = __shfl_xor_sync(0xffffffffu, s, o);
        float nm = fmaxf(m, om);
        s = s * __expf(m - nm) + os * __expf(om - nm);
        m = nm;
    }
    if ((t & 31) == 0) { redm[t >> 5] = m; reds[t >> 5] = s; }
    __syncthreads();
    if (t == 0) {
        float fm = redm[0], fs = reds[0];
#pragma unroll
        for (int w = 1; w < 8; w++) {
            float om = redm[w], os = reds[w];
            float nm = fmaxf(fm, om);
            fs = fs * __expf(fm - nm) + os * __expf(om - nm);
            fm = nm;
        }
        g_RMAX[base + lrow] = fm;
        g_RINV[base + lrow] = 1.0f / fs;
    }
}

// ---------------------------------------------------------------------------
// Kernel 4: enhanced chunk = softmax(logits) @ XT.
//   A-loader applies exp((l - rmax)) * rinv while staging to smem.
//   M=QCHUNK, N=CCH, K=NTOK.  B (g_LIN[0]) is K x N row-major (N contiguous).
// ---------------------------------------------------------------------------
__global__ __launch_bounds__(256) void attn_pv_kernel(int base)
{
    const float* __restrict__ Bmat = g_LIN[0];

    __shared__ float As[BK][BM + PAD];
    __shared__ float Bs[BK][BNT + PAD];

    const int lm0 = blockIdx.y * BM;
    const int m0  = base + lm0;
    const int n0  = blockIdx.x * BNT;
    const int t   = threadIdx.x;
    const int tx = t % 16, ty = t / 16;

    const int arow = t / 4;    // 0..63 (+64)
    const int akv  = t % 4;
    const int bk   = t / 16;   // 0..15
    const int bcv  = t % 16;

    const float rmax0 = g_RMAX[m0 + arow];
    const float rinv0 = g_RINV[m0 + arow];
    const float rmax1 = g_RMAX[m0 + arow + 64];
    const float rinv1 = g_RINV[m0 + arow + 64];

    float acc[TM][TN];
#pragma unroll
    for (int i = 0; i < TM; i++)
#pragma unroll
        for (int j = 0; j < TN; j++) acc[i][j] = 0.f;

    for (int k0 = 0; k0 < NTOK; k0 += BK) {
        {
            int m = arow;
            float4 a4 = *(const float4*)(g_LOGITS + (size_t)(lm0 + m) * NTOK + k0 + 4 * akv);
            As[4 * akv + 0][m] = __expf(a4.x - rmax0) * rinv0;
            As[4 * akv + 1][m] = __expf(a4.y - rmax0) * rinv0;
            As[4 * akv + 2][m] = __expf(a4.z - rmax0) * rinv0;
            As[4 * akv + 3][m] = __expf(a4.w - rmax0) * rinv0;
            m = arow + 64;
            float4 c4 = *(const float4*)(g_LOGITS + (size_t)(lm0 + m) * NTOK + k0 + 4 * akv);
            As[4 * akv + 0][m] = __expf(c4.x - rmax1) * rinv1;
            As[4 * akv + 1][m] = __expf(c4.y - rmax1) * rinv1;
            As[4 * akv + 2][m] = __expf(c4.z - rmax1) * rinv1;
            As[4 * akv + 3][m] = __expf(c4.w - rmax1) * rinv1;
        }
        {
            const float* bp = Bmat + (size_t)(k0 + bk) * CCH + n0;
            float4 b0 = *(const float4*)(bp + 4 * bcv);
            float4 b1 = *(const float4*)(bp + 4 * bcv + 64);
            *(float4*)&Bs[bk][4 * bcv]      = b0;
            *(float4*)&Bs[bk][4 * bcv + 64] = b1;
        }
        __syncthreads();
#pragma unroll
        for (int k = 0; k < BK; k++) {
            float af[TM], bf[TN];
#pragma unroll
            for (int i = 0; i < TM; i++) af[i] = As[k][ty * TM + i];
#pragma unroll
            for (int j = 0; j < TN; j++) bf[j] = Bs[k][tx * TN + j];
#pragma unroll
            for (int i = 0; i < TM; i++)
#pragma unroll
                for (int j = 0; j < TN; j++)
                    acc[i][j] = fmaf(af[i], bf[j], acc[i][j]);
        }
        __syncthreads();
    }

#pragma unroll
    for (int i = 0; i < TM; i++) {
        int m = m0 + ty * TM + i;
        float* op = g_ENH + (size_t)m * CCH + n0 + tx * TN;
        *(float4*)(op)     = make_float4(acc[i][0], acc[i][1], acc[i][2], acc[i][3]);
        *(float4*)(op + 4) = make_float4(acc[i][4], acc[i][5], acc[i][6], acc[i][7]);
    }
}

// ---------------------------------------------------------------------------
// Kernel 5: decoder 1x1 conv.  Y[n][o] = sum_c ENH[n][c] * w_dec[o][c] + b_dec[o]
// ---------------------------------------------------------------------------
__global__ __launch_bounds__(256) void dec_kernel(
    const float* __restrict__ w_dec, const float* __restrict__ b_dec)
{
    __shared__ float As[BK][BM + PAD];
    __shared__ float Bs[BK][BNT + PAD];

    const int m0 = blockIdx.y * BM;
    const int n0 = blockIdx.x * BNT;
    const int t  = threadIdx.x;
    const int tx = t % 16, ty = t / 16;
    const int row = t / 4;
    const int kv  = t % 4;

    float acc[TM][TN];
#pragma unroll
    for (int i = 0; i < TM; i++)
#pragma unroll
        for (int j = 0; j < TN; j++) acc[i][j] = 0.f;

    for (int k0 = 0; k0 < CCH; k0 += BK) {
#pragma unroll
        for (int r = 0; r < 2; r++) {
            int m = row + r * 64;
            float4 a4 = *(const float4*)(g_ENH + (size_t)(m0 + m) * CCH + k0 + 4 * kv);
            As[4 * kv + 0][m] = a4.x;
            As[4 * kv + 1][m] = a4.y;
            As[4 * kv + 2][m] = a4.z;
            As[4 * kv + 3][m] = a4.w;
            int n = row + r * 64;
            float4 b4 = *(const float4*)(w_dec + (size_t)(n0 + n) * CCH + k0 + 4 * kv);
            Bs[4 * kv + 0][n] = b4.x;
            Bs[4 * kv + 1][n] = b4.y;
            Bs[4 * kv + 2][n] = b4.z;
            Bs[4 * kv + 3][n] = b4.w;
        }
        __syncthreads();
#pragma unroll
        for (int k = 0; k < BK; k++) {
            float af[TM], bf[TN];
#pragma unroll
            for (int i = 0; i < TM; i++) af[i] = As[k][ty * TM + i];
#pragma unroll
            for (int j = 0; j < TN; j++) bf[j] = Bs[k][tx * TN + j];
#pragma unroll
            for (int i = 0; i < TM; i++)
#pragma unroll
                for (int j = 0; j < TN; j++)
                    acc[i][j] = fmaf(af[i], bf[j], acc[i][j]);
        }
        __syncthreads();
    }

#pragma unroll
    for (int i = 0; i < TM; i++) {
        int m = m0 + ty * TM + i;
        float* op = g_Y + (size_t)m * CCH + n0 + tx * TN;
#pragma unroll
        for (int j = 0; j < TN; j++) op[j] = acc[i][j] + b_dec[n0 + tx * TN + j];
    }
}

// ---------------------------------------------------------------------------
// Kernel 6: BN partial sums. 72 blocks x 128 tokens, deterministic (no atomics)
// ---------------------------------------------------------------------------
__global__ __launch_bounds__(256) void bn_partial_kernel()
{
    const int blk = blockIdx.x;
    const int t = threadIdx.x;
    const int c0 = t * 2;
    float s0 = 0.f, s1 = 0.f, q0 = 0.f, q1 = 0.f;
    const float* yp = g_Y + (size_t)blk * 128 * CCH;
    for (int n = 0; n < 128; n++) {
        float2 v = *(const float2*)(yp + (size_t)n * CCH + c0);
        s0 += v.x; s1 += v.y;
        q0 += v.x * v.x; q1 += v.y * v.y;
    }
    g_PART[blk * CCH + c0]     = s0;
    g_PART[blk * CCH + c0 + 1] = s1;
    g_PART[72 * CCH + blk * CCH + c0]     = q0;
    g_PART[72 * CCH + blk * CCH + c0 + 1] = q1;
}

// ---------------------------------------------------------------------------
// Kernel 7: BN reduce -> per-channel scale/shift
// ---------------------------------------------------------------------------
__global__ __launch_bounds__(512) void bn_reduce_kernel(
    const float* __restrict__ gamma, const float* __restrict__ beta)
{
    const int c = threadIdx.x;
    float s = 0.f, q = 0.f;
    for (int b = 0; b < 72; b++) {
        s += g_PART[b * CCH + c];
        q += g_PART[72 * CCH + b * CCH + c];
    }
    const float inv_n = 1.0f / (float)NTOK;
    float mean = s * inv_n;
    float var  = q * inv_n - mean * mean;
    float rstd = rsqrtf(var + BN_EPS);
    float sc = gamma[c] * rstd;
    g_SCALE[c] = sc;
    g_SHIFT[c] = beta[c] - mean * sc;
}

// ---------------------------------------------------------------------------
// Kernel 8: affine + ReLU + transpose to (B,C,H,W) via smem tiles
// ---------------------------------------------------------------------------
__global__ __launch_bounds__(256) void final_kernel(float* __restrict__ out)
{
    __shared__ float sm[32][33];
    const int hw0 = blockIdx.x * 32;
    const int c0  = blockIdx.y * 32;
    const int b   = blockIdx.z;
    const int tx = threadIdx.x;   // 0..31
    const int ty = threadIdx.y;   // 0..7

#pragma unroll
    for (int s = 0; s < 4; s++) {
        int tok = b * HW + hw0 + ty + 8 * s;
        sm[ty + 8 * s][tx] = g_Y[(size_t)tok * CCH + c0 + tx];
    }
    __syncthreads();
#pragma unroll
    for (int s = 0; s < 4; s++) {
        int c = c0 + ty + 8 * s;
        float v = sm[tx][ty + 8 * s] * g_SCALE[c] + g_SHIFT[c];
        out[((size_t)b * CCH + c) * HW + hw0 + tx] = fmaxf(v, 0.f);
    }
}

// ---------------------------------------------------------------------------
extern "C" void kernel_launch(void* const* d_in, const int* in_sizes, int n_in,
                              void* d_out, int out_size)
{
    const float* x     = (const float*)d_in[0];
    const float* dep   = (const float*)d_in[1];
    const float* w_rgb = (const float*)d_in[2];
    const float* b_rgb = (const float*)d_in[3];
    const float* w_lhs = (const float*)d_in[4];
    const float* b_lhs = (const float*)d_in[5];
    const float* w_rhs = (const float*)d_in[6];
    const float* b_rhs = (const float*)d_in[7];
    const float* w_dec = (const float*)d_in[8];
    const float* b_dec = (const float*)d_in[9];
    const float* gamma = (const float*)d_in[10];
    const float* beta  = (const float*)d_in[11];
    float* out = (float*)d_out;

    // 1) xt / lhs / rhs linears (A read straight from BCHW layout)
    linear_kernel<<<dim3(CCH / BNT, NTOK / BM, 3), 256>>>(
        x, dep, w_rgb, b_rgb, w_lhs, b_lhs, w_rhs, b_rhs);

    // 2-4) attention, chunked over query rows to bound scratch memory
    for (int c = 0; c < NCHUNK; c++) {
        int base = c * QCHUNK;
        logits_kernel<<<dim3(NTOK / BNT, QCHUNK / BM), 256>>>(base);
        softmax_kernel<<<QCHUNK, 256>>>(base);
        attn_pv_kernel<<<dim3(CCH / BNT, QCHUNK / BM), 256>>>(base);
    }

    // 5) decoder linear
    dec_kernel<<<dim3(CCH / BNT, NTOK / BM), 256>>>(w_dec, b_dec);

    // 6,7) BatchNorm stats (deterministic two-stage)
    bn_partial_kernel<<<72, 256>>>();
    bn_reduce_kernel<<<1, 512>>>(gamma, beta);

    // 8) normalize + ReLU + layout transform to (B,C,H,W)
    final_kernel<<<dim3(HW / 32, CCH / 32, BATCH), dim3(32, 8)>>>(out);
}

// round 8
// speedup vs baseline: 2.8094x; 2.8094x over previous
#include <cuda_runtime.h>
#include <cuda_bf16.h>
#include <math.h>
#include <stdint.h>

// Problem constants
#define NTOK   9216      // B*H*W tokens
#define CCH    512       // channels
#define HW     2304      // H*W
#define BATCH  4
#define BN_EPS 1e-5f

// Attention row-chunking
#define QCHUNK 1152
#define NCHUNK (NTOK / QCHUNK)      // 8
#define SPLITK 4

// fp32 SIMT GEMM tile config (linears/decoder)
#define BM 128
#define BNT 128
#define BK 16
#define TM 8
#define TN 8
#define PAD 4

// ---------------------------------------------------------------------------
// Static device scratch (~175 MB; row-major everywhere now)
// ---------------------------------------------------------------------------
__device__ __align__(16) __nv_bfloat16 g_LHS_H[NTOK * CCH];   // [tok][ch]
__device__ __align__(16) __nv_bfloat16 g_LHS_L[NTOK * CCH];
__device__ __align__(16) __nv_bfloat16 g_RHS_H[NTOK * CCH];   // [tok][ch]
__device__ __align__(16) __nv_bfloat16 g_RHS_L[NTOK * CCH];
__device__ __align__(16) __nv_bfloat16 g_XT_H[NTOK * CCH];    // [ch][tok]
__device__ __align__(16) __nv_bfloat16 g_XT_L[NTOK * CCH];
// Pool: P_H | P_L (chunk probs, bf16 hi/lo, row-major [QCHUNK][NTOK]).
// Y (fp32 [NTOK][CCH]) aliases the pool after the last PV.
__device__ float4 g_PPOOL[(size_t)QCHUNK * NTOK * 4 / 16];    // 42.5 MB
#define P_H_PTR ((__nv_bfloat16*)g_PPOOL)
#define P_L_PTR (((__nv_bfloat16*)g_PPOOL) + (size_t)QCHUNK * NTOK)
#define Y_PTR   ((float*)g_PPOOL)
__device__ float g_ENHP[SPLITK][NTOK * CCH];                  // 75.5 MB
__device__ float g_PART[2 * 72 * CCH];
__device__ float g_SCALE[CCH];
__device__ float g_SHIFT[CCH];

// ---------------------------------------------------------------------------
// helpers
// ---------------------------------------------------------------------------
__device__ __forceinline__ void split_bf16(float v, __nv_bfloat16& h, __nv_bfloat16& l) {
    h = __float2bfloat16(v);
    l = __float2bfloat16(v - __bfloat162float(h));
}
__device__ __forceinline__ uint32_t pack_bf2(__nv_bfloat16 a, __nv_bfloat16 b) {
    __nv_bfloat162 t = __halves2bfloat162(a, b);
    return *(uint32_t*)&t;
}
__device__ __forceinline__ void unpack8(uint4 hu, uint4 lu, float* v) {
    const uint32_t* hp = &hu.x;
    const uint32_t* lp = &lu.x;
#pragma unroll
    for (int w = 0; w < 4; ++w) {
        __nv_bfloat162 h2 = *(__nv_bfloat162*)&hp[w];
        __nv_bfloat162 l2 = *(__nv_bfloat162*)&lp[w];
        v[2 * w]     = __bfloat162float(h2.x) + __bfloat162float(l2.x);
        v[2 * w + 1] = __bfloat162float(h2.y) + __bfloat162float(l2.y);
    }
}
__device__ __forceinline__ uint32_t smem_u32(const void* p) {
    uint32_t a;
    asm("{ .reg .u64 t; cvta.to.shared.u64 t, %1; cvt.u32.u64 %0, t; }" : "=r"(a) : "l"(p));
    return a;
}
__device__ __forceinline__ void cpa16(uint32_t dst, const void* src) {
    asm volatile("cp.async.cg.shared.global [%0], [%1], 16;" :: "r"(dst), "l"(src) : "memory");
}
__device__ __forceinline__ void cpa_commit() {
    asm volatile("cp.async.commit_group;" ::: "memory");
}
__device__ __forceinline__ void ldsm_x4(uint32_t addr, uint32_t& r0, uint32_t& r1,
                                        uint32_t& r2, uint32_t& r3) {
    asm volatile("ldmatrix.sync.aligned.m8n8.x4.shared.b16 {%0,%1,%2,%3}, [%4];"
                 : "=r"(r0), "=r"(r1), "=r"(r2), "=r"(r3) : "r"(addr));
}
__device__ __forceinline__ void mma_bf16(float* d, const uint32_t* a, const uint32_t* b) {
    asm volatile(
        "mma.sync.aligned.m16n8k16.row.col.f32.bf16.bf16.f32 "
        "{%0,%1,%2,%3}, {%4,%5,%6,%7}, {%8,%9}, {%0,%1,%2,%3};"
        : "+f"(d[0]), "+f"(d[1]), "+f"(d[2]), "+f"(d[3])
        : "r"(a[0]), "r"(a[1]), "r"(a[2]), "r"(a[3]), "r"(b[0]), "r"(b[1]));
}

// ---------------------------------------------------------------------------
// mma.sync split-bf16 GEMM.  CTA tile 128x128, 8 warps (2M x 4N, 64x32 each),
// BK=32, 2-stage cp.async.  smem rows padded to 40 elems (80B) -> ldmatrix
// conflict-free.  C = (Ah+Al) @ (Bh+Bl)^T  (3 terms: hh + lh + hl).
//   mode 0: logits -> P hi/lo row-major [QCHUNK][NTOK]
//   mode 1: PV     -> g_ENHP[z] fp32 [NTOK][CCH], split-K over blockIdx.z
// ---------------------------------------------------------------------------
#define MAT_BYTES (128 * 80)               // 10240 per matrix (128 rows x 40 elems)
#define STAGE_BYTES (4 * MAT_BYTES)        // Ah | Al | Bh | Bl
#define GEMM_SMEM (2 * STAGE_BYTES)        // 81920

__device__ __forceinline__ void stage_load(uint32_t sdst, int tid,
                                           const __nv_bfloat16* Ah, const __nv_bfloat16* Al,
                                           const __nv_bfloat16* Bh, const __nv_bfloat16* Bl,
                                           int arow, int brow, int k0, int lda, int ldb) {
    const int r = tid >> 2;          // 0..63
    const int seg = tid & 3;         // 16B segment (8 elems)
#pragma unroll
    for (int h = 0; h < 2; ++h) {
        const int row = r + h * 64;
        const uint32_t so = row * 80 + seg * 16;
        const size_t ga = (size_t)(arow + row) * lda + k0 + seg * 8;
        const size_t gb = (size_t)(brow + row) * ldb + k0 + seg * 8;
        cpa16(sdst + 0 * MAT_BYTES + so, Ah + ga);
        cpa16(sdst + 1 * MAT_BYTES + so, Al + ga);
        cpa16(sdst + 2 * MAT_BYTES + so, Bh + gb);
        cpa16(sdst + 3 * MAT_BYTES + so, Bl + gb);
    }
}

__global__ void __launch_bounds__(256, 1) mma_gemm_kernel(int mode, int base)
{
    extern __shared__ char smem[];
    const uint32_t sb = smem_u32(smem);
    const int tid = threadIdx.x;
    const int wid = tid >> 5;
    const int lane = tid & 31;
    const int wm = wid & 1;          // 2 M-blocks of 64
    const int wn = wid >> 1;         // 4 N-blocks of 32
    const int n0 = blockIdx.x * 128;

    const __nv_bfloat16 *Ah, *Al, *Bh, *Bl;
    int lda, ldb, arow, brow, kc, kb;
    if (mode == 0) {
        Ah = g_LHS_H; Al = g_LHS_L; Bh = g_RHS_H; Bl = g_RHS_L;
        lda = CCH; ldb = CCH;
        arow = base + blockIdx.y * 128; brow = n0;
        kc = CCH / 32; kb = 0;
    } else {
        Ah = P_H_PTR; Al = P_L_PTR; Bh = g_XT_H; Bl = g_XT_L;
        lda = NTOK; ldb = NTOK;
        arow = blockIdx.y * 128; brow = n0;
        kc = NTOK / 32 / SPLITK;                  // 72
        kb = blockIdx.z * (NTOK / SPLITK);        // k element offset
    }

    float acc[4][4][4];
#pragma unroll
    for (int t = 0; t < 4; ++t)
#pragma unroll
        for (int j = 0; j < 4; ++j)
#pragma unroll
            for (int q = 0; q < 4; ++q) acc[t][j][q] = 0.f;

    // ldmatrix lane address components
    const int g = lane >> 3, l = lane & 7;
    const int a_row_off = (g & 1) * 8 + l;        // within m16 tile
    const int a_col_off = (g >> 1) * 8;           // within k16
    const int b_row_off = (g >> 1) * 8 + l;       // within n16 tile
    const int b_col_off = (g & 1) * 8;

    // prologue
    stage_load(sb, tid, Ah, Al, Bh, Bl, arow, brow, kb, lda, ldb);
    cpa_commit();

    for (int c = 0; c < kc; ++c) {
        if (c + 1 < kc) {
            stage_load(sb + ((c + 1) & 1) * STAGE_BYTES, tid, Ah, Al, Bh, Bl,
                       arow, brow, kb + (c + 1) * 32, lda, ldb);
            cpa_commit();
            asm volatile("cp.async.wait_group 1;" ::: "memory");
        } else {
            asm volatile("cp.async.wait_group 0;" ::: "memory");
        }
        __syncthreads();

        const uint32_t st = sb + (c & 1) * STAGE_BYTES;
#pragma unroll
        for (int ko = 0; ko < 32; ko += 16) {
            uint32_t fAh[4][4], fAl[4][4], fBh[2][4], fBl[2][4];
#pragma unroll
            for (int t = 0; t < 4; ++t) {
                const uint32_t ra = st + (wm * 64 + t * 16 + a_row_off) * 80
                                  + (ko + a_col_off) * 2;
                ldsm_x4(ra + 0 * MAT_BYTES, fAh[t][0], fAh[t][1], fAh[t][2], fAh[t][3]);
                ldsm_x4(ra + 1 * MAT_BYTES, fAl[t][0], fAl[t][1], fAl[t][2], fAl[t][3]);
            }
#pragma unroll
            for (int u = 0; u < 2; ++u) {
                const uint32_t rb = st + (wn * 32 + u * 16 + b_row_off) * 80
                                  + (ko + b_col_off) * 2;
                ldsm_x4(rb + 2 * MAT_BYTES, fBh[u][0], fBh[u][1], fBh[u][2], fBh[u][3]);
                ldsm_x4(rb + 3 * MAT_BYTES, fBl[u][0], fBl[u][1], fBl[u][2], fBl[u][3]);
            }
#pragma unroll
            for (int t = 0; t < 4; ++t)
#pragma unroll
                for (int u = 0; u < 2; ++u)
#pragma unroll
                    for (int nh = 0; nh < 2; ++nh) {
                        float* d = acc[t][u * 2 + nh];
                        mma_bf16(d, fAh[t], &fBh[u][nh * 2]);   // hi*hi
                        mma_bf16(d, fAl[t], &fBh[u][nh * 2]);   // lo*hi
                        mma_bf16(d, fAh[t], &fBl[u][nh * 2]);   // hi*lo
                    }
        }
        __syncthreads();
    }

    // Epilogue.  Reg (q0,q1): row = tbase + lane/4, cols col0,col0+1.
    //            Reg (q2,q3): row + 8.
    const int rbase = wm * 64 + (lane >> 2);
    const int cbase = wn * 32 + (lane & 3) * 2;
    if (mode == 0) {
        char* ph = (char*)P_H_PTR;
        char* pl = (char*)P_L_PTR;
        const int lrow0 = blockIdx.y * 128;
#pragma unroll
        for (int t = 0; t < 4; ++t)
#pragma unroll
            for (int j = 0; j < 4; ++j)
#pragma unroll
                for (int hrow = 0; hrow < 2; ++hrow) {
                    const int r = lrow0 + rbase + t * 16 + hrow * 8;
                    const int cg = n0 + cbase + j * 8;
                    const float v0 = acc[t][j][hrow * 2];
                    const float v1 = acc[t][j][hrow * 2 + 1];
                    __nv_bfloat16 h0, l0, h1, l1;
                    split_bf16(v0, h0, l0);
                    split_bf16(v1, h1, l1);
                    const size_t off = ((size_t)r * NTOK + cg) * 2;
                    *(uint32_t*)(ph + off) = pack_bf2(h0, h1);
                    *(uint32_t*)(pl + off) = pack_bf2(l0, l1);
                }
    } else {
        float* Cf = &g_ENHP[blockIdx.z][0];
        const int crow0 = base + blockIdx.y * 128;
#pragma unroll
        for (int t = 0; t < 4; ++t)
#pragma unroll
            for (int j = 0; j < 4; ++j)
#pragma unroll
                for (int hrow = 0; hrow < 2; ++hrow) {
                    const int r = crow0 + rbase + t * 16 + hrow * 8;
                    const int cg = n0 + cbase + j * 8;
                    *(float2*)(Cf + (size_t)r * CCH + cg) =
                        make_float2(acc[t][j][hrow * 2], acc[t][j][hrow * 2 + 1]);
                }
    }
}

// ---------------------------------------------------------------------------
// Kernel 1: input 1x1 convs (fp32 SIMT) -> bf16 hi/lo row-major.
//   which==0 -> XT transposed ([ch][tok]); 1 -> LHS; 2 -> RHS ([tok][ch]).
// ---------------------------------------------------------------------------
__global__ __launch_bounds__(256) void linear_kernel(
    const float* __restrict__ x, const float* __restrict__ dep,
    const float* __restrict__ w_rgb, const float* __restrict__ b_rgb,
    const float* __restrict__ w_lhs, const float* __restrict__ b_lhs,
    const float* __restrict__ w_rhs, const float* __restrict__ b_rhs)
{
    const int which = blockIdx.z;
    const float* __restrict__ A    = (which == 0) ? x : dep;
    const float* __restrict__ W    = (which == 0) ? w_rgb : (which == 1 ? w_lhs : w_rhs);
    const float* __restrict__ bias = (which == 0) ? b_rgb : (which == 1 ? b_lhs : b_rhs);

    __shared__ float As[BK][BM + PAD];
    __shared__ float Bs[BK][BNT + PAD];

    const int m0 = blockIdx.y * BM;
    const int n0 = blockIdx.x * BNT;
    const int b  = m0 / HW;
    const int hw0 = m0 % HW;
    const int t  = threadIdx.x;
    const int tx = t % 16, ty = t / 16;

    const int lk  = t / 16;
    const int lcv = t % 16;
    const int brow = t / 4;
    const int bkv  = t % 4;

    float acc[TM][TN];
#pragma unroll
    for (int i = 0; i < TM; i++)
#pragma unroll
        for (int j = 0; j < TN; j++) acc[i][j] = 0.f;

    for (int k0 = 0; k0 < CCH; k0 += BK) {
        const float* ap = A + ((size_t)(b * CCH + k0 + lk)) * HW + hw0;
        float4 a0 = *(const float4*)(ap + 4 * lcv);
        float4 a1 = *(const float4*)(ap + 4 * lcv + 64);
        *(float4*)&As[lk][4 * lcv]      = a0;
        *(float4*)&As[lk][4 * lcv + 64] = a1;
#pragma unroll
        for (int r = 0; r < 2; r++) {
            int n = brow + r * 64;
            float4 w4 = *(const float4*)(W + (size_t)(n0 + n) * CCH + k0 + 4 * bkv);
            Bs[4 * bkv + 0][n] = w4.x;
            Bs[4 * bkv + 1][n] = w4.y;
            Bs[4 * bkv + 2][n] = w4.z;
            Bs[4 * bkv + 3][n] = w4.w;
        }
        __syncthreads();
#pragma unroll
        for (int k = 0; k < BK; k++) {
            float af[TM], bf[TN];
#pragma unroll
            for (int i = 0; i < TM; i++) af[i] = As[k][ty * TM + i];
#pragma unroll
            for (int j = 0; j < TN; j++) bf[j] = Bs[k][tx * TN + j];
#pragma unroll
            for (int i = 0; i < TM; i++)
#pragma unroll
                for (int j = 0; j < TN; j++)
                    acc[i][j] = fmaf(af[i], bf[j], acc[i][j]);
        }
        __syncthreads();
    }

    if (which == 0) {
        // XT [ch][tok]: pack pairs along token (i) dimension
        char* oh = (char*)g_XT_H;
        char* ol = (char*)g_XT_L;
#pragma unroll
        for (int j = 0; j < TN; j++) {
            int n = n0 + tx * TN + j;
            float bs = bias[n];
#pragma unroll
            for (int i = 0; i < TM; i += 2) {
                int m = m0 + ty * TM + i;
                float v0 = acc[i][j] + bs;
                float v1 = acc[i + 1][j] + bs;
                __nv_bfloat16 h0, l0, h1, l1;
                split_bf16(v0, h0, l0);
                split_bf16(v1, h1, l1);
                const size_t off = ((size_t)n * NTOK + m) * 2;
                *(uint32_t*)(oh + off) = pack_bf2(h0, h1);
                *(uint32_t*)(ol + off) = pack_bf2(l0, l1);
            }
        }
    } else {
        char* oh = (char*)((which == 1) ? g_LHS_H : g_RHS_H);
        char* ol = (char*)((which == 1) ? g_LHS_L : g_RHS_L);
#pragma unroll
        for (int i = 0; i < TM; i++) {
            int m = m0 + ty * TM + i;
#pragma unroll
            for (int j = 0; j < TN; j += 2) {
                int n = n0 + tx * TN + j;
                float v0 = acc[i][j] + bias[n];
                float v1 = acc[i][j + 1] + bias[n + 1];
                __nv_bfloat16 h0, l0, h1, l1;
                split_bf16(v0, h0, l0);
                split_bf16(v1, h1, l1);
                const size_t off = ((size_t)m * CCH + n) * 2;
                *(uint32_t*)(oh + off) = pack_bf2(h0, h1);
                *(uint32_t*)(ol + off) = pack_bf2(l0, l1);
            }
        }
    }
}

// ---------------------------------------------------------------------------
// Fused softmax + prob transform, IN PLACE on row-major hi/lo P.
// ---------------------------------------------------------------------------
__global__ __launch_bounds__(256) void softmax_prep_kernel()
{
    const int row = blockIdx.x;          // chunk-local row
    const int t = threadIdx.x;
    uint4* ph = (uint4*)(P_H_PTR + (size_t)row * NTOK);
    uint4* pl = (uint4*)(P_L_PTR + (size_t)row * NTOK);
    __shared__ float redm[8], reds[8];
    __shared__ float fin[2];

    float m = -3.4e38f, s = 0.f;
    for (int i = t; i < NTOK / 8; i += 256) {
        uint4 hu = ph[i], lu = pl[i];
        float v[8];
        unpack8(hu, lu, v);
        float vm = v[0];
#pragma unroll
        for (int k = 1; k < 8; k++) vm = fmaxf(vm, v[k]);
        float nm = fmaxf(m, vm);
        float add = 0.f;
#pragma unroll
        for (int k = 0; k < 8; k++) add += __expf(v[k] - nm);
        s = s * __expf(m - nm) + add;
        m = nm;
    }
#pragma unroll
    for (int o = 16; o; o >>= 1) {
        float om = __shfl_xor_sync(0xffffffffu, m, o);
        float os = __shfl_xor_sync(0xffffffffu, s, o);
        float nm = fmaxf(m, om);
        s = s * __expf(m - nm) + os * __expf(om - nm);
        m = nm;
    }
    if ((t & 31) == 0) { redm[t >> 5] = m; reds[t >> 5] = s; }
    __syncthreads();
    if (t == 0) {
        float fm = redm[0], fs = reds[0];
#pragma unroll
        for (int w = 1; w < 8; w++) {
            float om = redm[w], os = reds[w];
            float nm = fmaxf(fm, om);
            fs = fs * __expf(fm - nm) + os * __expf(om - nm);
            fm = nm;
        }
        fin[0] = fm;
        fin[1] = 1.0f / fs;
    }
    __syncthreads();
    const float fm = fin[0], ri = fin[1];

    for (int i = t; i < NTOK / 8; i += 256) {
        uint4 hu = ph[i], lu = pl[i];
        float v[8];
        unpack8(hu, lu, v);
        uint32_t ho[4], lo[4];
#pragma unroll
        for (int p = 0; p < 4; p++) {
            float p0 = __expf(v[2 * p] - fm) * ri;
            float p1 = __expf(v[2 * p + 1] - fm) * ri;
            __nv_bfloat16 h0, l0v, h1, l1v;
            split_bf16(p0, h0, l0v);
            split_bf16(p1, h1, l1v);
            ho[p] = pack_bf2(h0, h1);
            lo[p] = pack_bf2(l0v, l1v);
        }
        ph[i] = make_uint4(ho[0], ho[1], ho[2], ho[3]);
        pl[i] = make_uint4(lo[0], lo[1], lo[2], lo[3]);
    }
}

// ---------------------------------------------------------------------------
// Kernel 5: decoder 1x1 conv (fp32 SIMT); A = sum of SPLITK partials.
// ---------------------------------------------------------------------------
__global__ __launch_bounds__(256) void dec_kernel(
    const float* __restrict__ w_dec, const float* __restrict__ b_dec)
{
    __shared__ float As[BK][BM + PAD];
    __shared__ float Bs[BK][BNT + PAD];

    const int m0 = blockIdx.y * BM;
    const int n0 = blockIdx.x * BNT;
    const int t  = threadIdx.x;
    const int tx = t % 16, ty = t / 16;
    const int row = t / 4;
    const int kv  = t % 4;

    float acc[TM][TN];
#pragma unroll
    for (int i = 0; i < TM; i++)
#pragma unroll
        for (int j = 0; j < TN; j++) acc[i][j] = 0.f;

    for (int k0 = 0; k0 < CCH; k0 += BK) {
#pragma unroll
        for (int r = 0; r < 2; r++) {
            int m = row + r * 64;
            size_t aoff = (size_t)(m0 + m) * CCH + k0 + 4 * kv;
            float4 a0 = *(const float4*)(&g_ENHP[0][0] + aoff);
            float4 a1 = *(const float4*)(&g_ENHP[1][0] + aoff);
            float4 a2 = *(const float4*)(&g_ENHP[2][0] + aoff);
            float4 a3 = *(const float4*)(&g_ENHP[3][0] + aoff);
            As[4 * kv + 0][m] = (a0.x + a1.x) + (a2.x + a3.x);
            As[4 * kv + 1][m] = (a0.y + a1.y) + (a2.y + a3.y);
            As[4 * kv + 2][m] = (a0.z + a1.z) + (a2.z + a3.z);
            As[4 * kv + 3][m] = (a0.w + a1.w) + (a2.w + a3.w);
            int n = row + r * 64;
            float4 b4 = *(const float4*)(w_dec + (size_t)(n0 + n) * CCH + k0 + 4 * kv);
            Bs[4 * kv + 0][n] = b4.x;
            Bs[4 * kv + 1][n] = b4.y;
            Bs[4 * kv + 2][n] = b4.z;
            Bs[4 * kv + 3][n] = b4.w;
        }
        __syncthreads();
#pragma unroll
        for (int k = 0; k < BK; k++) {
            float af[TM], bf[TN];
#pragma unroll
            for (int i = 0; i < TM; i++) af[i] = As[k][ty * TM + i];
#pragma unroll
            for (int j = 0; j < TN; j++) bf[j] = Bs[k][tx * TN + j];
#pragma unroll
            for (int i = 0; i < TM; i++)
#pragma unroll
                for (int j = 0; j < TN; j++)
                    acc[i][j] = fmaf(af[i], bf[j], acc[i][j]);
        }
        __syncthreads();
    }

#pragma unroll
    for (int i = 0; i < TM; i++) {
        int m = m0 + ty * TM + i;
        float* op = Y_PTR + (size_t)m * CCH + n0 + tx * TN;
#pragma unroll
        for (int j = 0; j < TN; j++) op[j] = acc[i][j] + b_dec[n0 + tx * TN + j];
    }
}

// ---------------------------------------------------------------------------
// BN stats (deterministic two-stage) + final transform
// ---------------------------------------------------------------------------
__global__ __launch_bounds__(256) void bn_partial_kernel()
{
    const int blk = blockIdx.x;
    const int t = threadIdx.x;
    const int c0 = t * 2;
    float s0 = 0.f, s1 = 0.f, q0 = 0.f, q1 = 0.f;
    const float* yp = Y_PTR + (size_t)blk * 128 * CCH;
    for (int n = 0; n < 128; n++) {
        float2 v = *(const float2*)(yp + (size_t)n * CCH + c0);
        s0 += v.x; s1 += v.y;
        q0 += v.x * v.x; q1 += v.y * v.y;
    }
    g_PART[blk * CCH + c0]     = s0;
    g_PART[blk * CCH + c0 + 1] = s1;
    g_PART[72 * CCH + blk * CCH + c0]     = q0;
    g_PART[72 * CCH + blk * CCH + c0 + 1] = q1;
}

__global__ __launch_bounds__(512) void bn_reduce_kernel(
    const float* __restrict__ gamma, const float* __restrict__ beta)
{
    const int c = threadIdx.x;
    float s = 0.f, q = 0.f;
    for (int b = 0; b < 72; b++) {
        s += g_PART[b * CCH + c];
        q += g_PART[72 * CCH + b * CCH + c];
    }
    const float inv_n = 1.0f / (float)NTOK;
    float mean = s * inv_n;
    float var  = q * inv_n - mean * mean;
    float rstd = rsqrtf(var + BN_EPS);
    float sc = gamma[c] * rstd;
    g_SCALE[c] = sc;
    g_SHIFT[c] = beta[c] - mean * sc;
}

__global__ __launch_bounds__(256) void final_kernel(float* __restrict__ out)
{
    __shared__ float sm[32][33];
    const int hw0 = blockIdx.x * 32;
    const int c0  = blockIdx.y * 32;
    const int b   = blockIdx.z;
    const int tx = threadIdx.x;
    const int ty = threadIdx.y;

#pragma unroll
    for (int s = 0; s < 4; s++) {
        int tok = b * HW + hw0 + ty + 8 * s;
        sm[ty + 8 * s][tx] = Y_PTR[(size_t)tok * CCH + c0 + tx];
    }
    __syncthreads();
#pragma unroll
    for (int s = 0; s < 4; s++) {
        int c = c0 + ty + 8 * s;
        float v = sm[tx][ty + 8 * s] * g_SCALE[c] + g_SHIFT[c];
        out[((size_t)b * CCH + c) * HW + hw0 + tx] = fmaxf(v, 0.f);
    }
}

// ---------------------------------------------------------------------------
extern "C" void kernel_launch(void* const* d_in, const int* in_sizes, int n_in,
                              void* d_out, int out_size)
{
    const float* x     = (const float*)d_in[0];
    const float* dep   = (const float*)d_in[1];
    const float* w_rgb = (const float*)d_in[2];
    const float* b_rgb = (const float*)d_in[3];
    const float* w_lhs = (const float*)d_in[4];
    const float* b_lhs = (const float*)d_in[5];
    const float* w_rhs = (const float*)d_in[6];
    const float* b_rhs = (const float*)d_in[7];
    const float* w_dec = (const float*)d_in[8];
    const float* b_dec = (const float*)d_in[9];
    const float* gamma = (const float*)d_in[10];
    const float* beta  = (const float*)d_in[11];
    float* out = (float*)d_out;

    cudaFuncSetAttribute(mma_gemm_kernel,
                         cudaFuncAttributeMaxDynamicSharedMemorySize, GEMM_SMEM);

    // 1) xt / lhs / rhs linears -> bf16 hi/lo row-major
    linear_kernel<<<dim3(CCH / BNT, NTOK / BM, 3), 256>>>(
        x, dep, w_rgb, b_rgb, w_lhs, b_lhs, w_rhs, b_rhs);

    // 2-4) attention, chunked; mma.sync split-bf16 GEMMs
    for (int c = 0; c < NCHUNK; c++) {
        int base = c * QCHUNK;
        mma_gemm_kernel<<<dim3(NTOK / 128, QCHUNK / 128, 1), 256, GEMM_SMEM>>>(0, base);
        softmax_prep_kernel<<<QCHUNK, 256>>>();
        mma_gemm_kernel<<<dim3(CCH / 128, QCHUNK / 128, SPLITK), 256, GEMM_SMEM>>>(1, base);
    }

    // 5) decoder linear (sums split-K partials; Y aliases P pool)
    dec_kernel<<<dim3(CCH / BNT, NTOK / BM), 256>>>(w_dec, b_dec);

    // 6,7) BatchNorm stats
    bn_partial_kernel<<<72, 256>>>();
    bn_reduce_kernel<<<1, 512>>>(gamma, beta);

    // 8) normalize + ReLU + layout transform
    final_kernel<<<dim3(HW / 32, CCH / 32, BATCH), dim3(32, 8)>>>(out);
}